// round 1
// baseline (speedup 1.0000x reference)
#include <cuda_runtime.h>
#include <cuda_bf16.h>
#include <cstdint>

// Problem dims (fixed by the reference)
#define BSZ   8
#define SEQ   1024
#define DMODEL 512
#define NHEAD 8
#define HDIM  64
#define NROWS (BSZ*SEQ)          // 8192
#define QKVD  (3*DMODEL)         // 1536

// ---------------------------------------------------------------------------
// Scratch (static device globals; no allocation allowed)
// ---------------------------------------------------------------------------
__device__ float g_qkv    [NROWS * QKVD];    // 50.3 MB
__device__ float g_attnout[NROWS * DMODEL];  // 16.8 MB
__device__ float g_x1     [NROWS * DMODEL];
__device__ float g_ff     [NROWS * DMODEL];
__device__ float g_ff2    [NROWS * DMODEL];
__device__ unsigned char g_mask[BSZ * SEQ * SEQ]; // 8.4 MB, normalized bool
__device__ int g_mask_kind;                  // 0=u8, 1=i32, 2=f32

// ---------------------------------------------------------------------------
// Mask dtype detection: scan first 64KB of raw bytes.
//  float32 True = 0x3F800000 -> byte 0x3F present
//  uint8   True = 0x01 at arbitrary byte offsets (offset%4 != 0 occurs)
//  int32   True = 0x01 only at offsets%4==0
// ---------------------------------------------------------------------------
__global__ void detect_mask_kernel(const unsigned char* __restrict__ m) {
    __shared__ int c3f, coff;
    if (threadIdx.x == 0) { c3f = 0; coff = 0; }
    __syncthreads();
    int l3f = 0, loff = 0;
    for (int i = threadIdx.x; i < 65536; i += blockDim.x) {
        unsigned char v = m[i];
        if (v == 0x3Fu) l3f++;
        if (v != 0u && (i & 3) != 0) loff++;
    }
    atomicAdd(&c3f, l3f);
    atomicAdd(&coff, loff);
    __syncthreads();
    if (threadIdx.x == 0) {
        if (c3f > 0)      g_mask_kind = 2;
        else if (coff > 0) g_mask_kind = 0;
        else               g_mask_kind = 1;
    }
}

__global__ void expand_mask_kernel(const void* __restrict__ m,
                                   unsigned char* __restrict__ out, int n) {
    int kind = g_mask_kind;
    int stride = gridDim.x * blockDim.x;
    for (int i = blockIdx.x * blockDim.x + threadIdx.x; i < n; i += stride) {
        unsigned char v;
        if (kind == 0)      v = (((const unsigned char*)m)[i] != 0);
        else if (kind == 1) v = (((const int*)m)[i] != 0);
        else                v = (((const float*)m)[i] != 0.0f);
        out[i] = v;
    }
}

// ---------------------------------------------------------------------------
// SGEMM: C[M,N] = A[M,K] @ B[K,N] + bias[N], optional ReLU.
// Block tile 128x128, K-tile 16, 256 threads, 8x8 per thread.
// M%128==0, N%128==0, K%16==0 guaranteed by our shapes.
// ---------------------------------------------------------------------------
template<bool RELU>
__global__ __launch_bounds__(256)
void sgemm_kernel(const float* __restrict__ A, const float* __restrict__ B,
                  const float* __restrict__ bias, float* __restrict__ C,
                  int M, int N, int K) {
    __shared__ float As[16][132];   // [k][m], padded
    __shared__ float Bs[16][128];   // [k][n]

    const int bm = blockIdx.y * 128;
    const int bn = blockIdx.x * 128;
    const int tid = threadIdx.x;
    const int tx = tid & 15;        // 0..15 -> 8 cols each
    const int ty = tid >> 4;        // 0..15 -> 8 rows each

    float acc[8][8];
#pragma unroll
    for (int i = 0; i < 8; i++)
#pragma unroll
        for (int j = 0; j < 8; j++) acc[i][j] = 0.0f;

    for (int k0 = 0; k0 < K; k0 += 16) {
        // Load A tile: 128 rows x 16 cols = 512 float4
#pragma unroll
        for (int it = 0; it < 2; it++) {
            int f = tid + it * 256;
            int row = f >> 2;
            int kk = (f & 3) << 2;
            float4 v = *(const float4*)&A[(size_t)(bm + row) * K + k0 + kk];
            As[kk + 0][row] = v.x;
            As[kk + 1][row] = v.y;
            As[kk + 2][row] = v.z;
            As[kk + 3][row] = v.w;
        }
        // Load B tile: 16 rows x 128 cols = 512 float4
#pragma unroll
        for (int it = 0; it < 2; it++) {
            int f = tid + it * 256;
            int row = f >> 5;
            int n4 = (f & 31) << 2;
            *(float4*)&Bs[row][n4] =
                *(const float4*)&B[(size_t)(k0 + row) * N + bn + n4];
        }
        __syncthreads();

#pragma unroll
        for (int kk = 0; kk < 16; kk++) {
            float4 a0 = *(const float4*)&As[kk][ty * 8];
            float4 a1 = *(const float4*)&As[kk][ty * 8 + 4];
            float4 b0 = *(const float4*)&Bs[kk][tx * 8];
            float4 b1 = *(const float4*)&Bs[kk][tx * 8 + 4];
            float a[8] = {a0.x, a0.y, a0.z, a0.w, a1.x, a1.y, a1.z, a1.w};
            float b[8] = {b0.x, b0.y, b0.z, b0.w, b1.x, b1.y, b1.z, b1.w};
#pragma unroll
            for (int i = 0; i < 8; i++)
#pragma unroll
                for (int j = 0; j < 8; j++) acc[i][j] += a[i] * b[j];
        }
        __syncthreads();
    }

    // Epilogue
    float bs[8];
    {
        float4 v0 = *(const float4*)&bias[bn + tx * 8];
        float4 v1 = *(const float4*)&bias[bn + tx * 8 + 4];
        bs[0] = v0.x; bs[1] = v0.y; bs[2] = v0.z; bs[3] = v0.w;
        bs[4] = v1.x; bs[5] = v1.y; bs[6] = v1.z; bs[7] = v1.w;
    }
#pragma unroll
    for (int i = 0; i < 8; i++) {
        float* cp = C + (size_t)(bm + ty * 8 + i) * N + bn + tx * 8;
        float cv[8];
#pragma unroll
        for (int j = 0; j < 8; j++) {
            float v = acc[i][j] + bs[j];
            if (RELU) v = fmaxf(v, 0.0f);
            cv[j] = v;
        }
        *(float4*)cp       = make_float4(cv[0], cv[1], cv[2], cv[3]);
        *(float4*)(cp + 4) = make_float4(cv[4], cv[5], cv[6], cv[7]);
    }
}

// ---------------------------------------------------------------------------
// Flash-style attention.
// Grid: (SEQ/64, BSZ*NHEAD). Block: 256 threads.
// Thread (r = tid/4, j = tid%4) owns query row r of the 64-row tile:
//   - Q chunk cols [j*16, j*16+16) in registers (pre-scaled by hd^-0.5)
//   - scores for k = i*4 + j (i=0..15) per 64-wide K tile
//   - output accumulator cols [j*16, j*16+16)
// Softmax state (m, l) replicated across the 4 lanes of a row via shfl.
// ---------------------------------------------------------------------------
__global__ __launch_bounds__(256)
void attn_kernel(const float* __restrict__ qkv,
                 const unsigned char* __restrict__ mask,
                 float* __restrict__ out) {
    __shared__ float Ks[64][65];   // padded: conflict-free strided reads
    __shared__ float Vs[64][64];   // unpadded: aligned float4 reads

    const int qt = blockIdx.x;           // query tile
    const int bh = blockIdx.y;
    const int b = bh >> 3, h = bh & 7;
    const int tid = threadIdx.x;
    const int r = tid >> 2;              // query row in tile
    const int j = tid & 3;               // lane group
    const int qrow = qt * 64 + r;
    const size_t grow = (size_t)b * SEQ + qrow;

    // Q chunk -> registers, pre-scaled
    float q[16];
    {
        const float* qp = qkv + grow * QKVD + h * HDIM + j * 16;
#pragma unroll
        for (int i4 = 0; i4 < 4; i4++) {
            float4 v = *(const float4*)(qp + i4 * 4);
            q[i4 * 4 + 0] = v.x * 0.125f;
            q[i4 * 4 + 1] = v.y * 0.125f;
            q[i4 * 4 + 2] = v.z * 0.125f;
            q[i4 * 4 + 3] = v.w * 0.125f;
        }
    }

    float O[16];
#pragma unroll
    for (int i = 0; i < 16; i++) O[i] = 0.0f;
    float m = -1e30f, l = 0.0f;

    const unsigned char* mrow = mask + ((size_t)b * SEQ + qrow) * SEQ;

    for (int kt = 0; kt < SEQ / 64; kt++) {
        // Load K/V tiles (each thread: one row quarter = 16 floats of each)
        {
            const int kr = tid >> 2;
            const int c = (tid & 3) * 16;
            const float* kp = qkv + ((size_t)b * SEQ + kt * 64 + kr) * QKVD
                              + DMODEL + h * HDIM + c;
            const float* vp = kp + DMODEL;
#pragma unroll
            for (int i4 = 0; i4 < 4; i4++) {
                float4 kv = *(const float4*)(kp + i4 * 4);
                Ks[kr][c + i4 * 4 + 0] = kv.x;
                Ks[kr][c + i4 * 4 + 1] = kv.y;
                Ks[kr][c + i4 * 4 + 2] = kv.z;
                Ks[kr][c + i4 * 4 + 3] = kv.w;
                *(float4*)&Vs[kr][c + i4 * 4] = *(const float4*)(vp + i4 * 4);
            }
        }
        __syncthreads();

        // Scores s[i] for k = i*4 + j
        float s[16];
        unsigned mb = 0;
#pragma unroll
        for (int i = 0; i < 16; i++) {
            s[i] = 0.0f;
            if (mrow[kt * 64 + i * 4 + j]) mb |= (1u << i);
        }
#pragma unroll
        for (int d = 0; d < HDIM; d++) {
            float qv = __shfl_sync(0xffffffffu, q[d & 15], d >> 4, 4);
#pragma unroll
            for (int i = 0; i < 16; i++)
                s[i] += qv * Ks[i * 4 + j][d];
        }
#pragma unroll
        for (int i = 0; i < 16; i++)
            if (mb & (1u << i)) s[i] = -1e30f;

        // Row max across this thread's 16 + the row's 4 lanes
        float tmax = s[0];
#pragma unroll
        for (int i = 1; i < 16; i++) tmax = fmaxf(tmax, s[i]);
        tmax = fmaxf(tmax, __shfl_xor_sync(0xffffffffu, tmax, 1, 4));
        tmax = fmaxf(tmax, __shfl_xor_sync(0xffffffffu, tmax, 2, 4));

        float mnew = fmaxf(m, tmax);
        float corr = __expf(m - mnew);

        float p[16];
        float ls = 0.0f;
#pragma unroll
        for (int i = 0; i < 16; i++) {
            float pi = (mb & (1u << i)) ? 0.0f : __expf(s[i] - mnew);
            p[i] = pi;
            ls += pi;
        }
        ls += __shfl_xor_sync(0xffffffffu, ls, 1, 4);
        ls += __shfl_xor_sync(0xffffffffu, ls, 2, 4);
        l = l * corr + ls;
        m = mnew;
#pragma unroll
        for (int i = 0; i < 16; i++) O[i] *= corr;

        // PV: O[dc] += p[k] * V[k][dc] for dc in this lane's 16 columns
#pragma unroll
        for (int k = 0; k < 64; k++) {
            float pv = __shfl_sync(0xffffffffu, p[k >> 2], k & 3, 4);
            const float4* vr = (const float4*)&Vs[k][j * 16];
#pragma unroll
            for (int c4 = 0; c4 < 4; c4++) {
                float4 v = vr[c4];
                O[c4 * 4 + 0] += pv * v.x;
                O[c4 * 4 + 1] += pv * v.y;
                O[c4 * 4 + 2] += pv * v.z;
                O[c4 * 4 + 3] += pv * v.w;
            }
        }
        __syncthreads();
    }

    const float inv = 1.0f / l;
    float* op = out + grow * DMODEL + h * HDIM + j * 16;
#pragma unroll
    for (int c4 = 0; c4 < 4; c4++) {
        *(float4*)(op + c4 * 4) = make_float4(O[c4 * 4 + 0] * inv,
                                              O[c4 * 4 + 1] * inv,
                                              O[c4 * 4 + 2] * inv,
                                              O[c4 * 4 + 3] * inv);
    }
}

// ---------------------------------------------------------------------------
// Residual + LayerNorm: out = LN(a + b) * gamma + beta, row width 512.
// One block (128 threads, float4 each) per row.
// ---------------------------------------------------------------------------
__global__ __launch_bounds__(128)
void ln_kernel(const float* __restrict__ a, const float* __restrict__ bb,
               const float* __restrict__ gamma, const float* __restrict__ beta,
               float* __restrict__ out) {
    __shared__ float red[4];
    const int row = blockIdx.x;
    const int tid = threadIdx.x;
    const size_t base = (size_t)row * DMODEL + tid * 4;

    float4 av = *(const float4*)(a + base);
    float4 bv = *(const float4*)(bb + base);
    float x0 = av.x + bv.x, x1 = av.y + bv.y;
    float x2 = av.z + bv.z, x3 = av.w + bv.w;

    float sum = x0 + x1 + x2 + x3;
#pragma unroll
    for (int o = 16; o; o >>= 1) sum += __shfl_xor_sync(0xffffffffu, sum, o);
    if ((tid & 31) == 0) red[tid >> 5] = sum;
    __syncthreads();
    float mean = (red[0] + red[1] + red[2] + red[3]) * (1.0f / DMODEL);
    __syncthreads();

    float d0 = x0 - mean, d1 = x1 - mean, d2 = x2 - mean, d3 = x3 - mean;
    float sq = d0 * d0 + d1 * d1 + d2 * d2 + d3 * d3;
#pragma unroll
    for (int o = 16; o; o >>= 1) sq += __shfl_xor_sync(0xffffffffu, sq, o);
    if ((tid & 31) == 0) red[tid >> 5] = sq;
    __syncthreads();
    float var = (red[0] + red[1] + red[2] + red[3]) * (1.0f / DMODEL);
    float rs = rsqrtf(var + 1e-5f);

    float4 gv = *(const float4*)(gamma + tid * 4);
    float4 be = *(const float4*)(beta + tid * 4);
    *(float4*)(out + base) = make_float4(d0 * rs * gv.x + be.x,
                                         d1 * rs * gv.y + be.y,
                                         d2 * rs * gv.z + be.z,
                                         d3 * rs * gv.w + be.w);
}

// ---------------------------------------------------------------------------
// Launch
// ---------------------------------------------------------------------------
extern "C" void kernel_launch(void* const* d_in, const int* in_sizes, int n_in,
                              void* d_out, int out_size) {
    const float* edge_x   = (const float*)d_in[0];
    const void*  edge_mask =               d_in[1];
    const float* Wqkv     = (const float*)d_in[2];
    const float* bqkv     = (const float*)d_in[3];
    const float* W1       = (const float*)d_in[4];
    const float* b1       = (const float*)d_in[5];
    const float* W2       = (const float*)d_in[6];
    const float* b2       = (const float*)d_in[7];
    const float* gamma1   = (const float*)d_in[8];
    const float* beta1    = (const float*)d_in[9];
    const float* gamma2   = (const float*)d_in[10];
    const float* beta2    = (const float*)d_in[11];
    float* out = (float*)d_out;

    float *qkv, *attnout, *x1, *ff, *ff2;
    unsigned char* mask;
    cudaGetSymbolAddress((void**)&qkv,     g_qkv);
    cudaGetSymbolAddress((void**)&attnout, g_attnout);
    cudaGetSymbolAddress((void**)&x1,      g_x1);
    cudaGetSymbolAddress((void**)&ff,      g_ff);
    cudaGetSymbolAddress((void**)&ff2,     g_ff2);
    cudaGetSymbolAddress((void**)&mask,    g_mask);

    const int nmask = BSZ * SEQ * SEQ;

    detect_mask_kernel<<<1, 256>>>((const unsigned char*)edge_mask);
    expand_mask_kernel<<<4096, 256>>>(edge_mask, mask, nmask);

    // QKV projection: [8192,512] @ [512,1536]
    sgemm_kernel<false><<<dim3(QKVD / 128, NROWS / 128), 256>>>(
        edge_x, Wqkv, bqkv, qkv, NROWS, QKVD, DMODEL);

    // Attention
    attn_kernel<<<dim3(SEQ / 64, BSZ * NHEAD), 256>>>(qkv, mask, attnout);

    // x1 = LN(edge_x + attnout)
    ln_kernel<<<NROWS, 128>>>(edge_x, attnout, gamma1, beta1, x1);

    // ff = relu(x1 @ W1 + b1)
    sgemm_kernel<true><<<dim3(DMODEL / 128, NROWS / 128), 256>>>(
        x1, W1, b1, ff, NROWS, DMODEL, DMODEL);

    // ff2 = ff @ W2 + b2
    sgemm_kernel<false><<<dim3(DMODEL / 128, NROWS / 128), 256>>>(
        ff, W2, b2, ff2, NROWS, DMODEL, DMODEL);

    // out = LN(x1 + ff2)
    ln_kernel<<<NROWS, 128>>>(x1, ff2, gamma2, beta2, out);
}

// round 2
// speedup vs baseline: 4.5740x; 4.5740x over previous
#include <cuda_runtime.h>
#include <cuda_bf16.h>
#include <cstdint>

#define BSZ    8
#define SEQ    1024
#define DMODEL 512
#define NHEAD  8
#define HDIM   64
#define NROWS  (BSZ*SEQ)          // 8192
#define QKVD   (3*DMODEL)         // 1536

// ---------------------------------------------------------------------------
// Scratch
// ---------------------------------------------------------------------------
__device__ float g_qkv     [NROWS * QKVD];
__device__ float g_attnout [NROWS * DMODEL];
__device__ float g_x1      [NROWS * DMODEL];
__device__ float g_ff      [NROWS * DMODEL];
__device__ float g_ff2     [NROWS * DMODEL];
__device__ unsigned int g_maskbits[NROWS * (SEQ/32)];  // 1 MB bitmask
__device__ int g_mask_kind;   // 0=u8, 1=i32, 2=f32

// ---------------------------------------------------------------------------
// helpers
// ---------------------------------------------------------------------------
__device__ __forceinline__ uint32_t f2tf32(float x) {
    uint32_t r;
    asm("cvt.rna.tf32.f32 %0, %1;" : "=r"(r) : "f"(x));
    return r;
}

__device__ __forceinline__ void mma_tf32(float d[4],
                                         const uint32_t a[4],
                                         const uint32_t b[2],
                                         const float c[4]) {
    asm volatile(
        "mma.sync.aligned.m16n8k8.row.col.f32.tf32.tf32.f32 "
        "{%0,%1,%2,%3}, {%4,%5,%6,%7}, {%8,%9}, {%10,%11,%12,%13};"
        : "=f"(d[0]), "=f"(d[1]), "=f"(d[2]), "=f"(d[3])
        : "r"(a[0]), "r"(a[1]), "r"(a[2]), "r"(a[3]),
          "r"(b[0]), "r"(b[1]),
          "f"(c[0]), "f"(c[1]), "f"(c[2]), "f"(c[3]));
}

// ---------------------------------------------------------------------------
// Mask dtype detection (scan first 64KB of raw bytes)
// ---------------------------------------------------------------------------
__global__ void detect_mask_kernel(const unsigned char* __restrict__ m) {
    __shared__ int c3f, coff;
    if (threadIdx.x == 0) { c3f = 0; coff = 0; }
    __syncthreads();
    int l3f = 0, loff = 0;
    for (int i = threadIdx.x; i < 65536; i += blockDim.x) {
        unsigned char v = m[i];
        if (v == 0x3Fu) l3f++;
        if (v != 0u && (i & 3) != 0) loff++;
    }
    atomicAdd(&c3f, l3f);
    atomicAdd(&coff, loff);
    __syncthreads();
    if (threadIdx.x == 0) {
        if (c3f > 0)       g_mask_kind = 2;
        else if (coff > 0) g_mask_kind = 0;
        else               g_mask_kind = 1;
    }
}

// Build bitmask: bit set => masked out. One bit per mask element via ballot.
__global__ void expand_mask_bits_kernel(const void* __restrict__ m,
                                        unsigned int* __restrict__ out, int n) {
    int kind = g_mask_kind;
    int stride = gridDim.x * blockDim.x;
    for (int i = blockIdx.x * blockDim.x + threadIdx.x; i < n; i += stride) {
        bool v;
        if (kind == 0)      v = (((const unsigned char*)m)[i] != 0);
        else if (kind == 1) v = (((const int*)m)[i] != 0);
        else                v = (((const float*)m)[i] != 0.0f);
        unsigned int bits = __ballot_sync(0xffffffffu, v);
        if ((threadIdx.x & 31) == 0) out[i >> 5] = bits;
    }
}

// ---------------------------------------------------------------------------
// tf32 MMA GEMM: C[M,N] = A[M,K] @ B[K,N] + bias, optional ReLU.
// Block 128x128, BK=16, 256 threads (8 warps as 4x2), warp tile 32x64.
// ---------------------------------------------------------------------------
#define GPAD 136   // 16-row smem pitch; 136 % 32 banks -> 8, conflict-free frags

template<bool RELU>
__global__ __launch_bounds__(256)
void mma_gemm_kernel(const float* __restrict__ A, const float* __restrict__ B,
                     const float* __restrict__ bias, float* __restrict__ C,
                     int M, int N, int K) {
    __shared__ uint32_t As[16 * GPAD];   // [k][m], tf32 bits
    __shared__ uint32_t Bs[16 * GPAD];   // [k][n], tf32 bits

    const int bm = blockIdx.y * 128;
    const int bn = blockIdx.x * 128;
    const int tid = threadIdx.x;
    const int wid = tid >> 5;
    const int lane = tid & 31;
    const int g = lane >> 2;      // groupID
    const int t = lane & 3;       // thread-in-group
    const int wm = (wid >> 1) * 32;
    const int wn = (wid & 1) * 64;

    float acc[2][8][4];
#pragma unroll
    for (int i = 0; i < 2; i++)
#pragma unroll
        for (int j = 0; j < 8; j++)
#pragma unroll
            for (int k = 0; k < 4; k++) acc[i][j][k] = 0.0f;

    for (int k0 = 0; k0 < K; k0 += 16) {
        // A tile: 128 rows x 16 k
#pragma unroll
        for (int it = 0; it < 2; it++) {
            int f = tid + it * 256;
            int row = f >> 2;
            int kk = (f & 3) << 2;
            float4 v = *(const float4*)&A[(size_t)(bm + row) * K + k0 + kk];
            As[(kk + 0) * GPAD + row] = f2tf32(v.x);
            As[(kk + 1) * GPAD + row] = f2tf32(v.y);
            As[(kk + 2) * GPAD + row] = f2tf32(v.z);
            As[(kk + 3) * GPAD + row] = f2tf32(v.w);
        }
        // B tile: 16 rows x 128 n
#pragma unroll
        for (int it = 0; it < 2; it++) {
            int f = tid + it * 256;
            int row = f >> 5;
            int n4 = (f & 31) << 2;
            float4 v = *(const float4*)&B[(size_t)(k0 + row) * N + bn + n4];
            uint4 u;
            u.x = f2tf32(v.x); u.y = f2tf32(v.y);
            u.z = f2tf32(v.z); u.w = f2tf32(v.w);
            *(uint4*)&Bs[row * GPAD + n4] = u;
        }
        __syncthreads();

#pragma unroll
        for (int ks = 0; ks < 16; ks += 8) {
            uint32_t af[2][4];
#pragma unroll
            for (int mt = 0; mt < 2; mt++) {
                int mrow = wm + mt * 16 + g;
                af[mt][0] = As[(ks + t) * GPAD + mrow];
                af[mt][1] = As[(ks + t) * GPAD + mrow + 8];
                af[mt][2] = As[(ks + t + 4) * GPAD + mrow];
                af[mt][3] = As[(ks + t + 4) * GPAD + mrow + 8];
            }
            uint32_t bf[8][2];
#pragma unroll
            for (int nt = 0; nt < 8; nt++) {
                int ncol = wn + nt * 8 + g;
                bf[nt][0] = Bs[(ks + t) * GPAD + ncol];
                bf[nt][1] = Bs[(ks + t + 4) * GPAD + ncol];
            }
#pragma unroll
            for (int mt = 0; mt < 2; mt++)
#pragma unroll
                for (int nt = 0; nt < 8; nt++)
                    mma_tf32(acc[mt][nt], af[mt], bf[nt], acc[mt][nt]);
        }
        __syncthreads();
    }

    // Epilogue
#pragma unroll
    for (int mt = 0; mt < 2; mt++) {
        int row = bm + wm + mt * 16 + g;
#pragma unroll
        for (int nt = 0; nt < 8; nt++) {
            int col = bn + wn + nt * 8 + 2 * t;
            float b0 = bias[col], b1 = bias[col + 1];
            float c0 = acc[mt][nt][0] + b0;
            float c1 = acc[mt][nt][1] + b1;
            float c2 = acc[mt][nt][2] + b0;
            float c3 = acc[mt][nt][3] + b1;
            if (RELU) {
                c0 = fmaxf(c0, 0.0f); c1 = fmaxf(c1, 0.0f);
                c2 = fmaxf(c2, 0.0f); c3 = fmaxf(c3, 0.0f);
            }
            *(float2*)&C[(size_t)row * N + col] = make_float2(c0, c1);
            *(float2*)&C[(size_t)(row + 8) * N + col] = make_float2(c2, c3);
        }
    }
}

// ---------------------------------------------------------------------------
// FlashAttention with tf32 mma.
// Block: 128 threads (4 warps). Each block: 64 query rows of one (b,h).
// Warp w: query rows [16w, 16w+16). K/V tiles of 64 keys in smem.
// S/P in C-fragments; P converted to A-fragments via quad shuffles.
// ---------------------------------------------------------------------------
#define PADK 68   // bank: (4*key + d) -> conflict-free for QK B-frags
#define PADV 72   // bank: (8*key + d) -> conflict-free for PV B-frags

__global__ __launch_bounds__(128)
void attn_mma_kernel(const float* __restrict__ qkv,
                     const unsigned int* __restrict__ maskbits,
                     float* __restrict__ out) {
    __shared__ uint32_t Ks[64 * PADK];
    __shared__ uint32_t Vs[64 * PADV];

    const int qt = blockIdx.x;
    const int bh = blockIdx.y;
    const int b = bh >> 3, h = bh & 7;
    const int tid = threadIdx.x;
    const int wid = tid >> 5;
    const int lane = tid & 31;
    const int g = lane >> 2;     // row within 8-row group
    const int t = lane & 3;
    const int r0 = wid * 16;     // warp's first query row in tile

    const int qrow_lo = qt * 64 + r0 + g;        // this thread's low row
    const size_t growL = (size_t)b * SEQ + qrow_lo;

    // Q fragments (pre-scaled by hd^-0.5 = 0.125, exact)
    uint32_t qa[8][4];
    {
        const float* qb = qkv + growL * QKVD + h * HDIM;
#pragma unroll
        for (int kk = 0; kk < 8; kk++) {
            int d0 = kk * 8 + t;
            qa[kk][0] = f2tf32(qb[d0] * 0.125f);
            qa[kk][1] = f2tf32(qb[8 * QKVD + d0] * 0.125f);
            qa[kk][2] = f2tf32(qb[d0 + 4] * 0.125f);
            qa[kk][3] = f2tf32(qb[8 * QKVD + d0 + 4] * 0.125f);
        }
    }

    float o[8][4];
#pragma unroll
    for (int j = 0; j < 8; j++)
#pragma unroll
        for (int k = 0; k < 4; k++) o[j][k] = 0.0f;
    float m_lo = -1e30f, m_hi = -1e30f, l_lo = 0.0f, l_hi = 0.0f;

    const unsigned int* mbL = maskbits + growL * (SEQ / 32);
    const unsigned int* mbH = mbL + 8 * (SEQ / 32);

    for (int kt = 0; kt < SEQ / 64; kt++) {
        __syncthreads();
        // Load K/V tiles (tf32-converted)
        {
            const float* kbase = qkv + ((size_t)b * SEQ + kt * 64) * QKVD
                                 + DMODEL + h * HDIM;
#pragma unroll
            for (int it = 0; it < 8; it++) {
                int f = tid + it * 128;          // 0..1023
                int row = f >> 4;
                int c4 = (f & 15) << 2;
                float4 kv = *(const float4*)(kbase + (size_t)row * QKVD + c4);
                float4 vv = *(const float4*)(kbase + (size_t)row * QKVD + DMODEL + c4);
                uint4 ku, vu;
                ku.x = f2tf32(kv.x); ku.y = f2tf32(kv.y);
                ku.z = f2tf32(kv.z); ku.w = f2tf32(kv.w);
                vu.x = f2tf32(vv.x); vu.y = f2tf32(vv.y);
                vu.z = f2tf32(vv.z); vu.w = f2tf32(vv.w);
                *(uint4*)&Ks[row * PADK + c4] = ku;
                *(uint4*)&Vs[row * PADV + c4] = vu;
            }
        }
        __syncthreads();

        // S = Q K^T  (8 n-tiles of 8 keys)
        float sc[8][4];
#pragma unroll
        for (int j = 0; j < 8; j++)
#pragma unroll
            for (int k = 0; k < 4; k++) sc[j][k] = 0.0f;
#pragma unroll
        for (int kk = 0; kk < 8; kk++) {
#pragma unroll
            for (int j = 0; j < 8; j++) {
                uint32_t bf[2];
                bf[0] = Ks[(j * 8 + g) * PADK + kk * 8 + t];
                bf[1] = Ks[(j * 8 + g) * PADK + kk * 8 + t + 4];
                mma_tf32(sc[j], qa[kk], bf, sc[j]);
            }
        }

        // Mask: bit set => masked. mflags bit (j*4+k) mirrors sc[j][k].
        unsigned int w0L = mbL[kt * 2], w1L = mbL[kt * 2 + 1];
        unsigned int w0H = mbH[kt * 2], w1H = mbH[kt * 2 + 1];
        unsigned int mflags = 0;
#pragma unroll
        for (int j = 0; j < 8; j++) {
            int cc = j * 8 + 2 * t;              // key col within tile (0..63)
            unsigned int wL = (cc < 32) ? w0L : w1L;
            unsigned int wH = (cc < 32) ? w0H : w1H;
            int bit = cc & 31;
            if ((wL >> bit) & 1u)       { sc[j][0] = -1e30f; mflags |= 1u << (j*4+0); }
            if ((wL >> (bit+1)) & 1u)   { sc[j][1] = -1e30f; mflags |= 1u << (j*4+1); }
            if ((wH >> bit) & 1u)       { sc[j][2] = -1e30f; mflags |= 1u << (j*4+2); }
            if ((wH >> (bit+1)) & 1u)   { sc[j][3] = -1e30f; mflags |= 1u << (j*4+3); }
        }

        // Row maxima (this thread + quad lanes)
        float tmax_lo = -1e30f, tmax_hi = -1e30f;
#pragma unroll
        for (int j = 0; j < 8; j++) {
            tmax_lo = fmaxf(tmax_lo, fmaxf(sc[j][0], sc[j][1]));
            tmax_hi = fmaxf(tmax_hi, fmaxf(sc[j][2], sc[j][3]));
        }
        tmax_lo = fmaxf(tmax_lo, __shfl_xor_sync(0xffffffffu, tmax_lo, 1, 4));
        tmax_lo = fmaxf(tmax_lo, __shfl_xor_sync(0xffffffffu, tmax_lo, 2, 4));
        tmax_hi = fmaxf(tmax_hi, __shfl_xor_sync(0xffffffffu, tmax_hi, 1, 4));
        tmax_hi = fmaxf(tmax_hi, __shfl_xor_sync(0xffffffffu, tmax_hi, 2, 4));

        float mnew_lo = fmaxf(m_lo, tmax_lo);
        float mnew_hi = fmaxf(m_hi, tmax_hi);
        float corr_lo = __expf(m_lo - mnew_lo);
        float corr_hi = __expf(m_hi - mnew_hi);

        // P = exp(S - m), masked forced to 0. Store tf32 bits in pc.
        uint32_t pc[8][4];
        float ls_lo = 0.0f, ls_hi = 0.0f;
#pragma unroll
        for (int j = 0; j < 8; j++) {
            float p0 = (mflags >> (j*4+0)) & 1u ? 0.0f : __expf(sc[j][0] - mnew_lo);
            float p1 = (mflags >> (j*4+1)) & 1u ? 0.0f : __expf(sc[j][1] - mnew_lo);
            float p2 = (mflags >> (j*4+2)) & 1u ? 0.0f : __expf(sc[j][2] - mnew_hi);
            float p3 = (mflags >> (j*4+3)) & 1u ? 0.0f : __expf(sc[j][3] - mnew_hi);
            ls_lo += p0 + p1;
            ls_hi += p2 + p3;
            pc[j][0] = f2tf32(p0); pc[j][1] = f2tf32(p1);
            pc[j][2] = f2tf32(p2); pc[j][3] = f2tf32(p3);
        }
        ls_lo += __shfl_xor_sync(0xffffffffu, ls_lo, 1, 4);
        ls_lo += __shfl_xor_sync(0xffffffffu, ls_lo, 2, 4);
        ls_hi += __shfl_xor_sync(0xffffffffu, ls_hi, 1, 4);
        ls_hi += __shfl_xor_sync(0xffffffffu, ls_hi, 2, 4);
        l_lo = l_lo * corr_lo + ls_lo;
        l_hi = l_hi * corr_hi + ls_hi;
        m_lo = mnew_lo; m_hi = mnew_hi;
#pragma unroll
        for (int j = 0; j < 8; j++) {
            o[j][0] *= corr_lo; o[j][1] *= corr_lo;
            o[j][2] *= corr_hi; o[j][3] *= corr_hi;
        }

        // O += P V : convert P (C-layout) -> A-layout via quad shuffles
        const int src  = (lane & ~3) | (t >> 1);
        const int src2 = src + 2;
#pragma unroll
        for (int ks = 0; ks < 8; ks++) {
            uint32_t a0, a1, a2, a3;
            {
                uint32_t v00 = __shfl_sync(0xffffffffu, pc[ks][0], src);
                uint32_t v01 = __shfl_sync(0xffffffffu, pc[ks][1], src);
                uint32_t v10 = __shfl_sync(0xffffffffu, pc[ks][0], src2);
                uint32_t v11 = __shfl_sync(0xffffffffu, pc[ks][1], src2);
                a0 = (t & 1) ? v01 : v00;
                a2 = (t & 1) ? v11 : v10;
                uint32_t w00 = __shfl_sync(0xffffffffu, pc[ks][2], src);
                uint32_t w01 = __shfl_sync(0xffffffffu, pc[ks][3], src);
                uint32_t w10 = __shfl_sync(0xffffffffu, pc[ks][2], src2);
                uint32_t w11 = __shfl_sync(0xffffffffu, pc[ks][3], src2);
                a1 = (t & 1) ? w01 : w00;
                a3 = (t & 1) ? w11 : w10;
            }
            uint32_t af[4] = {a0, a1, a2, a3};
#pragma unroll
            for (int j = 0; j < 8; j++) {
                uint32_t bf[2];
                bf[0] = Vs[(ks * 8 + t) * PADV + j * 8 + g];
                bf[1] = Vs[(ks * 8 + t + 4) * PADV + j * 8 + g];
                mma_tf32(o[j], af, bf, o[j]);
            }
        }
    }

    // Write normalized output
    const float inv_lo = 1.0f / l_lo;
    const float inv_hi = 1.0f / l_hi;
    float* obase = out + growL * DMODEL + h * HDIM;
#pragma unroll
    for (int j = 0; j < 8; j++) {
        int col = j * 8 + 2 * t;
        *(float2*)(obase + col) =
            make_float2(o[j][0] * inv_lo, o[j][1] * inv_lo);
        *(float2*)(obase + 8 * DMODEL + col) =
            make_float2(o[j][2] * inv_hi, o[j][3] * inv_hi);
    }
}

// ---------------------------------------------------------------------------
// Residual + LayerNorm (row width 512), 128 threads/row
// ---------------------------------------------------------------------------
__global__ __launch_bounds__(128)
void ln_kernel(const float* __restrict__ a, const float* __restrict__ bb,
               const float* __restrict__ gamma, const float* __restrict__ beta,
               float* __restrict__ out) {
    __shared__ float red[4];
    const int row = blockIdx.x;
    const int tid = threadIdx.x;
    const size_t base = (size_t)row * DMODEL + tid * 4;

    float4 av = *(const float4*)(a + base);
    float4 bv = *(const float4*)(bb + base);
    float x0 = av.x + bv.x, x1 = av.y + bv.y;
    float x2 = av.z + bv.z, x3 = av.w + bv.w;

    float sum = x0 + x1 + x2 + x3;
#pragma unroll
    for (int o = 16; o; o >>= 1) sum += __shfl_xor_sync(0xffffffffu, sum, o);
    if ((tid & 31) == 0) red[tid >> 5] = sum;
    __syncthreads();
    float mean = (red[0] + red[1] + red[2] + red[3]) * (1.0f / DMODEL);
    __syncthreads();

    float d0 = x0 - mean, d1 = x1 - mean, d2 = x2 - mean, d3 = x3 - mean;
    float sq = d0 * d0 + d1 * d1 + d2 * d2 + d3 * d3;
#pragma unroll
    for (int o = 16; o; o >>= 1) sq += __shfl_xor_sync(0xffffffffu, sq, o);
    if ((tid & 31) == 0) red[tid >> 5] = sq;
    __syncthreads();
    float var = (red[0] + red[1] + red[2] + red[3]) * (1.0f / DMODEL);
    float rs = rsqrtf(var + 1e-5f);

    float4 gv = *(const float4*)(gamma + tid * 4);
    float4 be = *(const float4*)(beta + tid * 4);
    *(float4*)(out + base) = make_float4(d0 * rs * gv.x + be.x,
                                         d1 * rs * gv.y + be.y,
                                         d2 * rs * gv.z + be.z,
                                         d3 * rs * gv.w + be.w);
}

// ---------------------------------------------------------------------------
// Launch
// ---------------------------------------------------------------------------
extern "C" void kernel_launch(void* const* d_in, const int* in_sizes, int n_in,
                              void* d_out, int out_size) {
    const float* edge_x    = (const float*)d_in[0];
    const void*  edge_mask =               d_in[1];
    const float* Wqkv      = (const float*)d_in[2];
    const float* bqkv      = (const float*)d_in[3];
    const float* W1        = (const float*)d_in[4];
    const float* b1        = (const float*)d_in[5];
    const float* W2        = (const float*)d_in[6];
    const float* b2        = (const float*)d_in[7];
    const float* gamma1    = (const float*)d_in[8];
    const float* beta1     = (const float*)d_in[9];
    const float* gamma2    = (const float*)d_in[10];
    const float* beta2     = (const float*)d_in[11];
    float* out = (float*)d_out;

    float *qkv, *attnout, *x1, *ff, *ff2;
    unsigned int* maskbits;
    cudaGetSymbolAddress((void**)&qkv,      g_qkv);
    cudaGetSymbolAddress((void**)&attnout,  g_attnout);
    cudaGetSymbolAddress((void**)&x1,       g_x1);
    cudaGetSymbolAddress((void**)&ff,       g_ff);
    cudaGetSymbolAddress((void**)&ff2,      g_ff2);
    cudaGetSymbolAddress((void**)&maskbits, g_maskbits);

    detect_mask_kernel<<<1, 256>>>((const unsigned char*)edge_mask);
    expand_mask_bits_kernel<<<4096, 256>>>(edge_mask, maskbits,
                                           BSZ * SEQ * SEQ);

    // QKV projection
    mma_gemm_kernel<false><<<dim3(QKVD / 128, NROWS / 128), 256>>>(
        edge_x, Wqkv, bqkv, qkv, NROWS, QKVD, DMODEL);

    // Attention
    attn_mma_kernel<<<dim3(SEQ / 64, BSZ * NHEAD), 128>>>(qkv, maskbits, attnout);

    // x1 = LN(edge_x + attnout)
    ln_kernel<<<NROWS, 128>>>(edge_x, attnout, gamma1, beta1, x1);

    // ff = relu(x1 @ W1 + b1)
    mma_gemm_kernel<true><<<dim3(DMODEL / 128, NROWS / 128), 256>>>(
        x1, W1, b1, ff, NROWS, DMODEL, DMODEL);

    // ff2 = ff @ W2 + b2
    mma_gemm_kernel<false><<<dim3(DMODEL / 128, NROWS / 128), 256>>>(
        ff, W2, b2, ff2, NROWS, DMODEL, DMODEL);

    // out = LN(x1 + ff2)
    ln_kernel<<<NROWS, 128>>>(x1, ff2, gamma2, beta2, out);
}